// round 2
// baseline (speedup 1.0000x reference)
#include <cuda_runtime.h>

// Fused 3-layer GraphConv, B=524288.
//   A_ENC:  agg[j]  = sum_{i=4j-3..4j+2} x[i mod 40]
//   A_PRED: agg2[j] = z1[j] + w*(z1[j-1] + z1[j+1]),  w = exp(-1/9)
//   A_DEC:  out[4k]=s[k], out[4k+1]=out[4k+2]=s[k]+s[k+1], out[4k+3]=s[k+1]
//           where s[j] = dot(relu(pred(z1)[j]), dec_rel_w)
//
// R2 changes vs R1 (230us, occ 17.9%, regs 168):
//  - rolling 3-node z1 window (+ saved z1[0], z1[1] for ring wrap): 40 live
//    z1 floats instead of 80 -> launch_bounds(128,4), <=128 regs
//  - packed fma.rn.f32x2 over feature pairs for all 8x8 matvecs (weights
//    pre-packed as float2 pairs in smem)

#define WPRED 0.8948393168143698f

union f2u { float2 f; unsigned long long u; };

__device__ __forceinline__ float2 ffma2(float2 a, float2 b, float2 c) {
    f2u A, B, C, D; A.f = a; B.f = b; C.f = c;
    asm("fma.rn.f32x2 %0, %1, %2, %3;" : "=l"(D.u) : "l"(A.u), "l"(B.u), "l"(C.u));
    return D.f;
}
__device__ __forceinline__ float2 fadd2(float2 a, float2 b) {
    f2u A, B, D; A.f = a; B.f = b;
    asm("add.rn.f32x2 %0, %1, %2;" : "=l"(D.u) : "l"(A.u), "l"(B.u));
    return D.f;
}

// encoder for one hidden node j: z1 pairs (features 2k,2k+1) in out[4]
__device__ __forceinline__ void enc_node(float aggj, const float* zrow8,
                                         const float2* __restrict__ wRoot,
                                         const float2* __restrict__ wErw,
                                         const float2* __restrict__ wErb,
                                         float2 out[4])
{
    float4 za = *(const float4*)&zrow8[0];
    float4 zb = *(const float4*)&zrow8[4];
    float zg[8] = {za.x, za.y, za.z, za.w, zb.x, zb.y, zb.z, zb.w};
    float2 ab = make_float2(aggj, aggj);
    float2 t[4];
    #pragma unroll
    for (int k = 0; k < 4; k++) t[k] = ffma2(ab, wErw[k], wErb[k]);
    #pragma unroll
    for (int g = 0; g < 8; g++) {
        float2 zbc = make_float2(zg[g], zg[g]);
        #pragma unroll
        for (int k = 0; k < 4; k++) t[k] = ffma2(zbc, wRoot[g * 4 + k], t[k]);
    }
    #pragma unroll
    for (int k = 0; k < 4; k++)
        out[k] = make_float2(fmaxf(t[k].x, 0.0f), fmaxf(t[k].y, 0.0f));
}

// predictor + dec_rel fold for one node: s = dot(relu(pred), dec_rel_w)
__device__ __forceinline__ float pred_s(const float2 zm[4], const float2 zc[4], const float2 zn[4],
                                        const float2* __restrict__ wPR,
                                        const float2* __restrict__ wPO,
                                        const float2* __restrict__ wPrb,
                                        const float2* __restrict__ wDrw)
{
    const float2 W2 = make_float2(WPRED, WPRED);
    float2 a2[4], t[4];
    #pragma unroll
    for (int k = 0; k < 4; k++) a2[k] = ffma2(W2, fadd2(zm[k], zn[k]), zc[k]);
    #pragma unroll
    for (int k = 0; k < 4; k++) t[k] = wPrb[k];
    #pragma unroll
    for (int g = 0; g < 8; g++) {
        float ag = (g & 1) ? a2[g >> 1].y : a2[g >> 1].x;
        float zg = (g & 1) ? zc[g >> 1].y : zc[g >> 1].x;
        float2 ab = make_float2(ag, ag);
        float2 zb = make_float2(zg, zg);
        #pragma unroll
        for (int k = 0; k < 4; k++) {
            t[k] = ffma2(ab, wPR[g * 4 + k], t[k]);
            t[k] = ffma2(zb, wPO[g * 4 + k], t[k]);
        }
    }
    float2 s2 = make_float2(0.0f, 0.0f);
    #pragma unroll
    for (int k = 0; k < 4; k++) {
        float2 r = make_float2(fmaxf(t[k].x, 0.0f), fmaxf(t[k].y, 0.0f));
        s2 = ffma2(r, wDrw[k], s2);
    }
    return s2.x + s2.y;
}

__global__ void __launch_bounds__(128, 4)
fused_gnn_kernel(const float* __restrict__ x,
                 const float* __restrict__ z,
                 const float* __restrict__ y,
                 const float* __restrict__ enc_rel_w,
                 const float* __restrict__ enc_rel_b,
                 const float* __restrict__ enc_root_w,
                 const float* __restrict__ pred_rel_w,
                 const float* __restrict__ pred_rel_b,
                 const float* __restrict__ pred_root_w,
                 const float* __restrict__ dec_rel_w,
                 const float* __restrict__ dec_rel_b,
                 const float* __restrict__ dec_root_w,
                 float* __restrict__ out,
                 long long B)
{
    __shared__ __align__(16) float2 wEncRoot[32];   // [g*4+k] = {W[2k][g], W[2k+1][g]}
    __shared__ __align__(16) float2 wPredRel[32];
    __shared__ __align__(16) float2 wPredRoot[32];
    __shared__ __align__(16) float2 wErw[4], wErb[4], wPrb[4], wDrw[4];
    __shared__ float sDrb, sDrt;
    __shared__ __align__(16) float4 sbuf4[4][672];  // per-warp tile: 32 rows x 84 floats

    const int tid = threadIdx.x;
    if (tid < 32) {
        int g = tid >> 2, k = tid & 3;
        wEncRoot[tid]  = make_float2(enc_root_w[(2 * k) * 8 + g],  enc_root_w[(2 * k + 1) * 8 + g]);
        wPredRel[tid]  = make_float2(pred_rel_w[(2 * k) * 8 + g],  pred_rel_w[(2 * k + 1) * 8 + g]);
        wPredRoot[tid] = make_float2(pred_root_w[(2 * k) * 8 + g], pred_root_w[(2 * k + 1) * 8 + g]);
    } else if (tid < 36) {
        int k = tid - 32;
        wErw[k] = make_float2(enc_rel_w[2 * k], enc_rel_w[2 * k + 1]);
        wErb[k] = make_float2(enc_rel_b[2 * k], enc_rel_b[2 * k + 1]);
        wPrb[k] = make_float2(pred_rel_b[2 * k], pred_rel_b[2 * k + 1]);
        wDrw[k] = make_float2(dec_rel_w[2 * k], dec_rel_w[2 * k + 1]);
    } else if (tid == 36) {
        sDrb = dec_rel_b[0]; sDrt = dec_root_w[0];
    }
    __syncthreads();

    const int warp = tid >> 5;
    const int lane = tid & 31;
    const long long e0 = ((long long)blockIdx.x * 4 + warp) * 32;
    if (e0 >= B) return;
    const int nval = (B - e0 >= 32) ? 32 : (int)(B - e0);
    float* buf = (float*)sbuf4[warp];

    // ===== stage x (coalesced), rows padded to 44 floats =====
    {
        const float4* xg = (const float4*)(x + e0 * 40);
        const int lim = nval * 10;
        #pragma unroll
        for (int k = 0; k < 10; k++) {
            int f4 = k * 32 + lane;
            if (f4 < lim) {
                float4 v = xg[f4];
                int e = f4 / 10, c = f4 % 10;
                *(float4*)&buf[e * 44 + c * 4] = v;
            }
        }
    }
    __syncwarp();

    float agg[10];
    if (lane < nval) {
        float xr[40];
        const float4* myx = (const float4*)&buf[lane * 44];
        #pragma unroll
        for (int k = 0; k < 10; k++) {
            float4 v = myx[k];
            xr[4*k] = v.x; xr[4*k+1] = v.y; xr[4*k+2] = v.z; xr[4*k+3] = v.w;
        }
        float p[20];
        #pragma unroll
        for (int i = 0; i < 20; i++) p[i] = xr[2*i] + xr[2*i+1];
        #pragma unroll
        for (int j = 0; j < 10; j++) {
            const int a  = (4*j - 3 + 40) % 40;
            const int b  = (4*j + 2) % 40;
            const int pm = (2*j - 1 + 20) % 20;
            agg[j] = xr[a] + p[pm] + p[2*j] + xr[b];
        }
    }
    __syncwarp();

    // ===== stage z (coalesced), rows padded to 84 floats =====
    {
        const float4* zg = (const float4*)(z + e0 * 80);
        const int lim = nval * 20;
        #pragma unroll
        for (int k = 0; k < 20; k++) {
            int f4 = k * 32 + lane;
            if (f4 < lim) {
                float4 v = zg[f4];
                int e = f4 / 20, c = f4 % 20;
                *(float4*)&buf[e * 84 + c * 4] = v;
            }
        }
    }
    __syncwarp();

    float s[10];
    if (lane < nval) {
        const float* zrow = &buf[lane * 84];
        // rolling z1 window: A=z1[j-1], Bw=z1[j], C=z1[j+1]; Z0=z1[0], Z1=z1[1]
        float2 A_[4], Bw[4], C_[4], Z0[4], Z1[4];
        enc_node(agg[0], zrow + 0 * 8, wEncRoot, wErw, wErb, A_);
        #pragma unroll
        for (int k = 0; k < 4; k++) Z0[k] = A_[k];
        enc_node(agg[1], zrow + 1 * 8, wEncRoot, wErw, wErb, Bw);
        #pragma unroll
        for (int k = 0; k < 4; k++) Z1[k] = Bw[k];

        #pragma unroll
        for (int j = 1; j <= 8; j++) {
            enc_node(agg[j + 1], zrow + (j + 1) * 8, wEncRoot, wErw, wErb, C_);
            s[j] = pred_s(A_, Bw, C_, wPredRel, wPredRoot, wPrb, wDrw);
            #pragma unroll
            for (int k = 0; k < 4; k++) { A_[k] = Bw[k]; Bw[k] = C_[k]; }
        }
        // A_=z1[8], Bw=z1[9]
        s[9] = pred_s(A_, Bw, Z0, wPredRel, wPredRoot, wPrb, wDrw);
        s[0] = pred_s(Bw, Z0, Z1, wPredRel, wPredRoot, wPrb, wDrw);
    }
    __syncwarp();

    // ===== stage y, compute out in place, store coalesced =====
    {
        const float4* yg = (const float4*)(y + e0 * 40);
        const int lim = nval * 10;
        #pragma unroll
        for (int k = 0; k < 10; k++) {
            int f4 = k * 32 + lane;
            if (f4 < lim) {
                float4 v = yg[f4];
                int e = f4 / 10, c = f4 % 10;
                *(float4*)&buf[e * 44 + c * 4] = v;
            }
        }
    }
    __syncwarp();

    if (lane < nval) {
        const float drb = sDrb, drt = sDrt;
        float4* myrow = (float4*)&buf[lane * 44];
        #pragma unroll
        for (int k = 0; k < 10; k++) {
            const int kp = (k + 1) % 10;
            const float c0 = s[k], c3 = s[kp];
            const float c12 = s[k] + s[kp];
            float4 v = myrow[k];
            v.x = fmaf(v.x, drt, drb) + c0;
            v.y = fmaf(v.y, drt, drb) + c12;
            v.z = fmaf(v.z, drt, drb) + c12;
            v.w = fmaf(v.w, drt, drb) + c3;
            myrow[k] = v;
        }
    }
    __syncwarp();

    {
        float4* og = (float4*)(out + e0 * 40);
        const int lim = nval * 10;
        #pragma unroll
        for (int k = 0; k < 10; k++) {
            int f4 = k * 32 + lane;
            if (f4 < lim) {
                int e = f4 / 10, c = f4 % 10;
                og[f4] = *(const float4*)&buf[e * 44 + c * 4];
            }
        }
    }
}

extern "C" void kernel_launch(void* const* d_in, const int* in_sizes, int n_in,
                              void* d_out, int out_size)
{
    const float* x          = (const float*)d_in[0];
    const float* z          = (const float*)d_in[1];
    const float* y          = (const float*)d_in[2];
    const float* enc_rel_w  = (const float*)d_in[3];
    const float* enc_rel_b  = (const float*)d_in[4];
    const float* enc_root_w = (const float*)d_in[5];
    const float* pred_rel_w = (const float*)d_in[6];
    const float* pred_rel_b = (const float*)d_in[7];
    const float* pred_root_w= (const float*)d_in[8];
    const float* dec_rel_w  = (const float*)d_in[9];
    const float* dec_rel_b  = (const float*)d_in[10];
    const float* dec_root_w = (const float*)d_in[11];

    const long long B = (long long)in_sizes[0] / 40;
    const int threads = 128;
    const long long elems_per_block = 128;
    const int blocks = (int)((B + elems_per_block - 1) / elems_per_block);

    fused_gnn_kernel<<<blocks, threads>>>(
        x, z, y, enc_rel_w, enc_rel_b, enc_root_w,
        pred_rel_w, pred_rel_b, pred_root_w,
        dec_rel_w, dec_rel_b, dec_root_w,
        (float*)d_out, B);
}

// round 3
// speedup vs baseline: 1.4247x; 1.4247x over previous
#include <cuda_runtime.h>

// Fused 3-layer GraphConv, B=524288.
//   A_ENC:  agg[j]  = sum_{i=4j-3..4j+2} x[i mod 40]
//   A_PRED: agg2[j] = z1[j] + w*(z1[j-1] + z1[j+1]),  w = exp(-1/9)
//   A_DEC:  out[4k]=s[k], out[4k+1]=out[4k+2]=s[k]+s[k+1], out[4k+3]=s[k+1]
//           where s[j] = dot(relu(pred(z1)[j]), dec_rel_w)
//
// R3: z1 lives in the shared tile (written in place of z) instead of
// registers -> ~95 regs, no spills (R2 spilled: 1.09GB DRAM traffic vs
// 400MB ideal). Predictor streams z1 through a 3-row register window,
// ring-wrap rows reloaded from smem. f32x2 packed FMA kept for matvecs.

#define WPRED 0.8948393168143698f

union f2u { float2 f; unsigned long long u; };

__device__ __forceinline__ float2 ffma2(float2 a, float2 b, float2 c) {
    f2u A, B, C, D; A.f = a; B.f = b; C.f = c;
    asm("fma.rn.f32x2 %0, %1, %2, %3;" : "=l"(D.u) : "l"(A.u), "l"(B.u), "l"(C.u));
    return D.f;
}
__device__ __forceinline__ float2 fadd2(float2 a, float2 b) {
    f2u A, B, D; A.f = a; B.f = b;
    asm("add.rn.f32x2 %0, %1, %2;" : "=l"(D.u) : "l"(A.u), "l"(B.u));
    return D.f;
}

// encoder for one node: reads z row (8 floats) from smem, writes z1 back in place
__device__ __forceinline__ void enc_node_inplace(float aggj, float* zrow8,
                                                 const float2* __restrict__ wRoot,
                                                 const float2* __restrict__ wErw,
                                                 const float2* __restrict__ wErb)
{
    float4 za = *(const float4*)&zrow8[0];
    float4 zb = *(const float4*)&zrow8[4];
    float zg[8] = {za.x, za.y, za.z, za.w, zb.x, zb.y, zb.z, zb.w};
    float2 ab = make_float2(aggj, aggj);
    float2 t[4];
    #pragma unroll
    for (int k = 0; k < 4; k++) t[k] = ffma2(ab, wErw[k], wErb[k]);
    #pragma unroll
    for (int g = 0; g < 8; g++) {
        float2 zbc = make_float2(zg[g], zg[g]);
        #pragma unroll
        for (int k = 0; k < 4; k++) t[k] = ffma2(zbc, wRoot[g * 4 + k], t[k]);
    }
    float4 o0 = make_float4(fmaxf(t[0].x, 0.f), fmaxf(t[0].y, 0.f),
                            fmaxf(t[1].x, 0.f), fmaxf(t[1].y, 0.f));
    float4 o1 = make_float4(fmaxf(t[2].x, 0.f), fmaxf(t[2].y, 0.f),
                            fmaxf(t[3].x, 0.f), fmaxf(t[3].y, 0.f));
    *(float4*)&zrow8[0] = o0;
    *(float4*)&zrow8[4] = o1;
}

__device__ __forceinline__ void load_row(const float* zrow8, float2 r[4]) {
    float4 a = *(const float4*)&zrow8[0];
    float4 b = *(const float4*)&zrow8[4];
    r[0] = make_float2(a.x, a.y); r[1] = make_float2(a.z, a.w);
    r[2] = make_float2(b.x, b.y); r[3] = make_float2(b.z, b.w);
}

// predictor + dec_rel fold: s = dot(relu(pred_center), dec_rel_w)
__device__ __forceinline__ float pred_s(const float2 zm[4], const float2 zc[4], const float2 zn[4],
                                        const float2* __restrict__ wPR,
                                        const float2* __restrict__ wPO,
                                        const float2* __restrict__ wPrb,
                                        const float2* __restrict__ wDrw)
{
    const float2 W2 = make_float2(WPRED, WPRED);
    float2 a2[4], t[4];
    #pragma unroll
    for (int k = 0; k < 4; k++) a2[k] = ffma2(W2, fadd2(zm[k], zn[k]), zc[k]);
    #pragma unroll
    for (int k = 0; k < 4; k++) t[k] = wPrb[k];
    #pragma unroll
    for (int g = 0; g < 8; g++) {
        float ag = (g & 1) ? a2[g >> 1].y : a2[g >> 1].x;
        float zg = (g & 1) ? zc[g >> 1].y : zc[g >> 1].x;
        float2 ab = make_float2(ag, ag);
        float2 zb = make_float2(zg, zg);
        #pragma unroll
        for (int k = 0; k < 4; k++) {
            t[k] = ffma2(ab, wPR[g * 4 + k], t[k]);
            t[k] = ffma2(zb, wPO[g * 4 + k], t[k]);
        }
    }
    float2 s2 = make_float2(0.0f, 0.0f);
    #pragma unroll
    for (int k = 0; k < 4; k++) {
        float2 r = make_float2(fmaxf(t[k].x, 0.0f), fmaxf(t[k].y, 0.0f));
        s2 = ffma2(r, wDrw[k], s2);
    }
    return s2.x + s2.y;
}

__global__ void __launch_bounds__(128, 4)
fused_gnn_kernel(const float* __restrict__ x,
                 const float* __restrict__ z,
                 const float* __restrict__ y,
                 const float* __restrict__ enc_rel_w,
                 const float* __restrict__ enc_rel_b,
                 const float* __restrict__ enc_root_w,
                 const float* __restrict__ pred_rel_w,
                 const float* __restrict__ pred_rel_b,
                 const float* __restrict__ pred_root_w,
                 const float* __restrict__ dec_rel_w,
                 const float* __restrict__ dec_rel_b,
                 const float* __restrict__ dec_root_w,
                 float* __restrict__ out,
                 long long B)
{
    __shared__ __align__(16) float2 wEncRoot[32];   // [g*4+k] = {W[2k][g], W[2k+1][g]}
    __shared__ __align__(16) float2 wPredRel[32];
    __shared__ __align__(16) float2 wPredRoot[32];
    __shared__ __align__(16) float2 wErw[4], wErb[4], wPrb[4], wDrw[4];
    __shared__ float sDrb, sDrt;
    __shared__ __align__(16) float4 sbuf4[4][672];  // per-warp tile: 32 rows x 84 floats

    const int tid = threadIdx.x;
    if (tid < 32) {
        int g = tid >> 2, k = tid & 3;
        wEncRoot[tid]  = make_float2(enc_root_w[(2 * k) * 8 + g],  enc_root_w[(2 * k + 1) * 8 + g]);
        wPredRel[tid]  = make_float2(pred_rel_w[(2 * k) * 8 + g],  pred_rel_w[(2 * k + 1) * 8 + g]);
        wPredRoot[tid] = make_float2(pred_root_w[(2 * k) * 8 + g], pred_root_w[(2 * k + 1) * 8 + g]);
    } else if (tid < 36) {
        int k = tid - 32;
        wErw[k] = make_float2(enc_rel_w[2 * k], enc_rel_w[2 * k + 1]);
        wErb[k] = make_float2(enc_rel_b[2 * k], enc_rel_b[2 * k + 1]);
        wPrb[k] = make_float2(pred_rel_b[2 * k], pred_rel_b[2 * k + 1]);
        wDrw[k] = make_float2(dec_rel_w[2 * k], dec_rel_w[2 * k + 1]);
    } else if (tid == 36) {
        sDrb = dec_rel_b[0]; sDrt = dec_root_w[0];
    }
    __syncthreads();

    const int warp = tid >> 5;
    const int lane = tid & 31;
    const long long e0 = ((long long)blockIdx.x * 4 + warp) * 32;
    if (e0 >= B) return;
    const int nval = (B - e0 >= 32) ? 32 : (int)(B - e0);
    float* buf = (float*)sbuf4[warp];

    // ===== stage x (coalesced, streaming), rows padded to 44 floats =====
    {
        const float4* xg = (const float4*)(x + e0 * 40);
        const int lim = nval * 10;
        #pragma unroll
        for (int k = 0; k < 10; k++) {
            int f4 = k * 32 + lane;
            if (f4 < lim) {
                float4 v = __ldcs(&xg[f4]);
                int e = f4 / 10, c = f4 % 10;
                *(float4*)&buf[e * 44 + c * 4] = v;
            }
        }
    }
    __syncwarp();

    float agg[10];
    if (lane < nval) {
        float xr[40];
        const float4* myx = (const float4*)&buf[lane * 44];
        #pragma unroll
        for (int k = 0; k < 10; k++) {
            float4 v = myx[k];
            xr[4*k] = v.x; xr[4*k+1] = v.y; xr[4*k+2] = v.z; xr[4*k+3] = v.w;
        }
        float p[20];
        #pragma unroll
        for (int i = 0; i < 20; i++) p[i] = xr[2*i] + xr[2*i+1];
        #pragma unroll
        for (int j = 0; j < 10; j++) {
            const int a  = (4*j - 3 + 40) % 40;
            const int b  = (4*j + 2) % 40;
            const int pm = (2*j - 1 + 20) % 20;
            agg[j] = xr[a] + p[pm] + p[2*j] + xr[b];
        }
    }
    __syncwarp();

    // ===== stage z (coalesced, streaming), rows padded to 84 floats =====
    {
        const float4* zg = (const float4*)(z + e0 * 80);
        const int lim = nval * 20;
        #pragma unroll
        for (int k = 0; k < 20; k++) {
            int f4 = k * 32 + lane;
            if (f4 < lim) {
                float4 v = __ldcs(&zg[f4]);
                int e = f4 / 20, c = f4 % 20;
                *(float4*)&buf[e * 84 + c * 4] = v;
            }
        }
    }
    __syncwarp();

    float s[10];
    if (lane < nval) {
        float* zrow = &buf[lane * 84];

        // encoder: z1[j] overwrites z[j] in smem (thread-private row)
        #pragma unroll
        for (int j = 0; j < 10; j++)
            enc_node_inplace(agg[j], zrow + j * 8, wEncRoot, wErw, wErb);

        // predictor: 3-row rolling window over smem z1
        float2 A_[4], Bw[4], C_[4];
        load_row(zrow + 0 * 8, A_);   // z1[0]
        load_row(zrow + 1 * 8, Bw);   // z1[1]
        #pragma unroll
        for (int j = 1; j <= 8; j++) {
            load_row(zrow + (j + 1) * 8, C_);
            s[j] = pred_s(A_, Bw, C_, wPredRel, wPredRoot, wPrb, wDrw);
            #pragma unroll
            for (int k = 0; k < 4; k++) { A_[k] = Bw[k]; Bw[k] = C_[k]; }
        }
        // A_=z1[8], Bw=z1[9]; wrap rows reloaded from smem
        load_row(zrow + 0 * 8, C_);                    // z1[0]
        s[9] = pred_s(A_, Bw, C_, wPredRel, wPredRoot, wPrb, wDrw);
        #pragma unroll
        for (int k = 0; k < 4; k++) A_[k] = C_[k];     // z1[0]
        load_row(zrow + 1 * 8, C_);                    // z1[1]
        s[0] = pred_s(Bw, A_, C_, wPredRel, wPredRoot, wPrb, wDrw);
    }
    __syncwarp();

    // ===== stage y, compute out in place, store coalesced =====
    {
        const float4* yg = (const float4*)(y + e0 * 40);
        const int lim = nval * 10;
        #pragma unroll
        for (int k = 0; k < 10; k++) {
            int f4 = k * 32 + lane;
            if (f4 < lim) {
                float4 v = __ldcs(&yg[f4]);
                int e = f4 / 10, c = f4 % 10;
                *(float4*)&buf[e * 44 + c * 4] = v;
            }
        }
    }
    __syncwarp();

    if (lane < nval) {
        const float drb = sDrb, drt = sDrt;
        float4* myrow = (float4*)&buf[lane * 44];
        #pragma unroll
        for (int k = 0; k < 10; k++) {
            const int kp = (k + 1) % 10;
            const float c0 = s[k], c3 = s[kp];
            const float c12 = s[k] + s[kp];
            float4 v = myrow[k];
            v.x = fmaf(v.x, drt, drb) + c0;
            v.y = fmaf(v.y, drt, drb) + c12;
            v.z = fmaf(v.z, drt, drb) + c12;
            v.w = fmaf(v.w, drt, drb) + c3;
            myrow[k] = v;
        }
    }
    __syncwarp();

    {
        float4* og = (float4*)(out + e0 * 40);
        const int lim = nval * 10;
        #pragma unroll
        for (int k = 0; k < 10; k++) {
            int f4 = k * 32 + lane;
            if (f4 < lim) {
                int e = f4 / 10, c = f4 % 10;
                __stcs(&og[f4], *(const float4*)&buf[e * 44 + c * 4]);
            }
        }
    }
}

extern "C" void kernel_launch(void* const* d_in, const int* in_sizes, int n_in,
                              void* d_out, int out_size)
{
    const float* x          = (const float*)d_in[0];
    const float* z          = (const float*)d_in[1];
    const float* y          = (const float*)d_in[2];
    const float* enc_rel_w  = (const float*)d_in[3];
    const float* enc_rel_b  = (const float*)d_in[4];
    const float* enc_root_w = (const float*)d_in[5];
    const float* pred_rel_w = (const float*)d_in[6];
    const float* pred_rel_b = (const float*)d_in[7];
    const float* pred_root_w= (const float*)d_in[8];
    const float* dec_rel_w  = (const float*)d_in[9];
    const float* dec_rel_b  = (const float*)d_in[10];
    const float* dec_root_w = (const float*)d_in[11];

    const long long B = (long long)in_sizes[0] / 40;
    const int threads = 128;
    const long long elems_per_block = 128;
    const int blocks = (int)((B + elems_per_block - 1) / elems_per_block);

    fused_gnn_kernel<<<blocks, threads>>>(
        x, z, y, enc_rel_w, enc_rel_b, enc_root_w,
        pred_rel_w, pred_rel_b, pred_root_w,
        dec_rel_w, dec_rel_b, dec_root_w,
        (float*)d_out, B);
}